// round 9
// baseline (speedup 1.0000x reference)
#include <cuda_runtime.h>
#include <cuda_fp16.h>
#include <stdint.h>
#include <math.h>

#define BATCH 4
#define SLEN  2048
#define EMBED 1024
#define NHEAD 16
#define HDIM  64
#define NTOK  (BATCH * SLEN)     // 8192
#define QKVN  (3 * EMBED)        // 3072

__device__ __half g_Q[(size_t)BATCH * NHEAD * SLEN * HDIM];   // pre-scaled by 1/32
__device__ __half g_K[(size_t)BATCH * NHEAD * SLEN * HDIM];
__device__ __half g_V[(size_t)BATCH * NHEAD * SLEN * HDIM];
__device__ __half g_xh[(size_t)NTOK * EMBED], g_xl[(size_t)NTOK * EMBED];
__device__ __half g_o[(size_t)NTOK * EMBED];
__device__ __half g_w1[(size_t)EMBED * QKVN];
__device__ __half g_w2[(size_t)EMBED * EMBED];

// ------------------------------ helpers ------------------------------------
__device__ __forceinline__ uint32_t s2u(const void* p) {
    uint32_t a;
    asm("{ .reg .u64 t; cvta.to.shared.u64 t, %1; cvt.u32.u64 %0, t; }" : "=r"(a) : "l"(p));
    return a;
}
__device__ __forceinline__ void mma_f16(float* d, const uint32_t* a, const uint32_t* b) {
    asm volatile("mma.sync.aligned.m16n8k16.row.col.f32.f16.f16.f32 "
        "{%0,%1,%2,%3},{%4,%5,%6,%7},{%8,%9},{%0,%1,%2,%3};"
        : "+f"(d[0]), "+f"(d[1]), "+f"(d[2]), "+f"(d[3])
        : "r"(a[0]), "r"(a[1]), "r"(a[2]), "r"(a[3]), "r"(b[0]), "r"(b[1]));
}
__device__ __forceinline__ void ldm_x4(uint32_t* r, uint32_t a) {
    asm volatile("ldmatrix.sync.aligned.m8n8.x4.shared.b16 {%0,%1,%2,%3},[%4];"
        : "=r"(r[0]), "=r"(r[1]), "=r"(r[2]), "=r"(r[3]) : "r"(a));
}
__device__ __forceinline__ void ldm_x4t(uint32_t* r, uint32_t a) {
    asm volatile("ldmatrix.sync.aligned.m8n8.x4.trans.shared.b16 {%0,%1,%2,%3},[%4];"
        : "=r"(r[0]), "=r"(r[1]), "=r"(r[2]), "=r"(r[3]) : "r"(a));
}
__device__ __forceinline__ uint32_t packh2(float a, float b) {
    __half2 h = __floats2half2_rn(a, b);
    return *(uint32_t*)&h;
}
__device__ __forceinline__ void split2h(float a, float b, uint32_t& hi, uint32_t& lo) {
    __half ha = __float2half_rn(a), hb = __float2half_rn(b);
    hi = (uint32_t)__half_as_ushort(ha) | ((uint32_t)__half_as_ushort(hb) << 16);
    lo = packh2(a - __half2float(ha), b - __half2float(hb));
}
#define CP16(sa, gp) \
    asm volatile("cp.async.cg.shared.global [%0], [%1], 16;" :: "r"(sa), "l"(gp) : "memory")
#define CP_COMMIT()  asm volatile("cp.async.commit_group;" ::: "memory")
#define CP_WAIT(n)   asm volatile("cp.async.wait_group %0;" :: "n"(n) : "memory")

// ------------------------- conversion kernels ------------------------------
__global__ void __launch_bounds__(256)
conv_split16(const float* __restrict__ X, __half* __restrict__ Xh,
             __half* __restrict__ Xl, int n4)
{
    int i = blockIdx.x * blockDim.x + threadIdx.x;
    if (i >= n4) return;
    float4 v = ((const float4*)X)[i];
    uint32_t h0, l0, h1, l1;
    split2h(v.x, v.y, h0, l0);
    split2h(v.z, v.w, h1, l1);
    ((uint2*)Xh)[i] = make_uint2(h0, h1);
    ((uint2*)Xl)[i] = make_uint2(l0, l1);
}
__global__ void __launch_bounds__(256)
conv_h(const float* __restrict__ X, __half* __restrict__ Y, int n4)
{
    int i = blockIdx.x * blockDim.x + threadIdx.x;
    if (i >= n4) return;
    float4 v = ((const float4*)X)[i];
    ((uint2*)Y)[i] = make_uint2(packh2(v.x, v.y), packh2(v.z, v.w));
}

// ---------------------------------------------------------------------------
// fp16 GEMM, TERMS-term A (hi[+lo]). BM=BN=128, BK=64 per stage, 3-stage
// cp.async pipeline, register fragment double-buffer across k-slices.
// 256 thr, 8 warps 2x4 (warp 64x32).
// MODE 0: de-interleave epilogue -> fp16 Q(scaled)/K/V.  MODE 1: fp32 store.
// ---------------------------------------------------------------------------
template <int MODE, int TERMS>
__global__ void __launch_bounds__(256)
gemm_f16(const __half* __restrict__ Ah, const __half* __restrict__ Al,
         const __half* __restrict__ B, float* __restrict__ C,
         __half* __restrict__ Qo, __half* __restrict__ Ko, __half* __restrict__ Vo,
         int M, int N, int K)
{
    constexpr uint32_t OFS_AL2 = 18432u;                       // 128 rows * 144B
    constexpr uint32_t OFSB = (TERMS == 2) ? 36864u : 18432u;
    constexpr uint32_t STGB = OFSB + 17408u;                   // + B: 64 rows * 272B

    extern __shared__ char gsm[];
    const uint32_t smb = s2u(gsm);

    const int tid = threadIdx.x, lane = tid & 31, warp = tid >> 5;
    const int wm = warp >> 2, wn = warp & 3;
    const int g = lane >> 2, t = lane & 3;
    const int m0 = blockIdx.y * 128, n0 = blockIdx.x * 128;

    const int arow = wm * 64 + (lane & 7) + ((lane >> 3) & 1) * 8;
    const int acol = (lane >> 4) * 8;
    const int brow = (lane & 7) + ((lane >> 3) & 1) * 8;
    const int bcol = (lane >> 4) * 8;

    float acc[4][4][4];
#pragma unroll
    for (int mt = 0; mt < 4; mt++)
#pragma unroll
        for (int nt = 0; nt < 4; nt++)
#pragma unroll
            for (int e = 0; e < 4; e++) acc[mt][nt][e] = 0.0f;

    const int KIT = K / 64;

    auto load_stage = [&](int it) {
        const uint32_t base = smb + (uint32_t)(it % 3) * STGB;
        const int k0 = it * 64;
#pragma unroll
        for (int r = 0; r < 4; r++) {                 // A: 128 rows x 64 halfs
            int id = tid + r * 256;
            int row = id >> 3, ch = id & 7;
            uint32_t da = base + (uint32_t)(row * 144 + ch * 16);
            size_t ga = (size_t)(m0 + row) * K + k0 + ch * 8;
            CP16(da, Ah + ga);
            if (TERMS == 2) CP16(da + OFS_AL2, Al + ga);
        }
#pragma unroll
        for (int r = 0; r < 4; r++) {                 // B: 64 rows x 128 halfs
            int id = tid + r * 256;
            int row = id >> 4, ch = id & 15;
            CP16(base + OFSB + (uint32_t)(row * 272 + ch * 16),
                 B + (size_t)(k0 + row) * N + n0 + ch * 8);
        }
        CP_COMMIT();
    };

    auto load_frags = [&](uint32_t cur, int ks, uint32_t (*fh)[4],
                          uint32_t (*fl)[4], uint32_t (*fbv)[4]) {
#pragma unroll
        for (int mt = 0; mt < 4; mt++) {
            uint32_t ad = cur + (uint32_t)((arow + mt * 16) * 144 + (acol + ks * 16) * 2);
            ldm_x4(fh[mt], ad);
            if (TERMS == 2) ldm_x4(fl[mt], ad + OFS_AL2);
        }
#pragma unroll
        for (int p = 0; p < 2; p++)
            ldm_x4t(fbv[p], cur + OFSB
                    + (uint32_t)((ks * 16 + brow) * 272 + (wn * 32 + p * 16 + bcol) * 2));
    };

    load_stage(0);
    load_stage(1);

    uint32_t fah[2][4][4], fal[2][4][4], fb[2][2][4];

#pragma unroll 1
    for (int it = 0; it < KIT; it++) {
        const uint32_t cur = smb + (uint32_t)(it % 3) * STGB;
        if (it + 2 < KIT) { load_stage(it + 2); CP_WAIT(2); }
        else if (it + 1 < KIT) { CP_WAIT(1); }
        else { CP_WAIT(0); }
        __syncthreads();

        load_frags(cur, 0, fah[0], fal[0], fb[0]);
#pragma unroll
        for (int ks = 0; ks < 4; ks++) {
            const int c = ks & 1;
            if (ks < 3) load_frags(cur, ks + 1, fah[c ^ 1], fal[c ^ 1], fb[c ^ 1]);
#pragma unroll
            for (int p = 0; p < 2; p++)
#pragma unroll
                for (int sub = 0; sub < 2; sub++) {
                    const int nt = 2 * p + sub;
#pragma unroll
                    for (int mt = 0; mt < 4; mt++) {
                        mma_f16(acc[mt][nt], fah[c][mt], &fb[c][p][sub * 2]);
                        if (TERMS == 2) mma_f16(acc[mt][nt], fal[c][mt], &fb[c][p][sub * 2]);
                    }
                }
        }
        __syncthreads();
    }

    if (MODE == 0) {
#pragma unroll
        for (int mt = 0; mt < 4; mt++)
#pragma unroll
            for (int nt = 0; nt < 4; nt++) {
                int r0 = m0 + wm * 64 + mt * 16 + g;
                int c0 = n0 + wn * 32 + nt * 8 + 2 * t;
#pragma unroll
                for (int e = 0; e < 4; e++) {
                    int row = r0 + (e >> 1) * 8;
                    int col = c0 + (e & 1);
                    int b_ = row >> 11, s = row & 2047;
                    int h = col / 192;
                    int rem = col - h * 192;
                    int d = rem / 3, w = rem - 3 * d;
                    __half* dst = (w == 0) ? Qo : (w == 1) ? Ko : Vo;
                    float sc = (w == 0) ? 0.03125f : 1.0f;
                    dst[(((size_t)b_ * NHEAD + h) * SLEN + s) * HDIM + d] =
                        __float2half_rn(acc[mt][nt][e] * sc);
                }
            }
    } else {
#pragma unroll
        for (int mt = 0; mt < 4; mt++)
#pragma unroll
            for (int nt = 0; nt < 4; nt++) {
                size_t r = (size_t)(m0 + wm * 64 + mt * 16 + g);
                int    c = n0 + wn * 32 + nt * 8 + 2 * t;
                *(float2*)&C[r * N + c]       = make_float2(acc[mt][nt][0], acc[mt][nt][1]);
                *(float2*)&C[(r + 8) * N + c] = make_float2(acc[mt][nt][2], acc[mt][nt][3]);
            }
    }
}

// ---------------------------------------------------------------------------
// Register FA2: BQ=128 (8 warps x 16 rows), BKEY=64, D=64.
// K/V 3-stage cp.async pipeline; S/P register-resident; x4 operand fetches.
// ---------------------------------------------------------------------------
#define LDHB 144
#define KVST (2 * 64 * LDHB)
#define ATTN_SMEM (128 * LDHB + 3 * KVST)

__global__ void __launch_bounds__(256, 2)
attn_reg(const __half* __restrict__ Q, const __half* __restrict__ K,
         const __half* __restrict__ V, __half* __restrict__ O)
{
    extern __shared__ char smc[];
    const uint32_t Qb = s2u(smc);
    const uint32_t KV0 = Qb + 128 * LDHB;

    const int tid = threadIdx.x, lane = tid & 31, warp = tid >> 5;
    const int g = lane >> 2, t = lane & 3;
    const int lr8 = (lane & 7) + ((lane >> 3) & 1) * 8;
    const int lc8 = (lane >> 4) * 8;
    const int qblk = blockIdx.x, bh = blockIdx.y;

    const __half* Qg = Q + ((size_t)bh * SLEN + qblk * 128) * HDIM;
    const __half* Kg = K + (size_t)bh * SLEN * HDIM;
    const __half* Vg = V + (size_t)bh * SLEN * HDIM;

    auto load_kv = [&](int kb) {
        const uint32_t base = KV0 + (uint32_t)(kb % 3) * KVST;
        const __half* Kgb = Kg + (size_t)kb * 64 * HDIM;
        const __half* Vgb = Vg + (size_t)kb * 64 * HDIM;
#pragma unroll
        for (int r = 0; r < 2; r++) {
            int id = tid + r * 256;
            int row = id >> 3, ch = id & 7;
            CP16(base + row * LDHB + ch * 16, Kgb + row * 64 + ch * 8);
            CP16(base + 64 * LDHB + row * LDHB + ch * 16, Vgb + row * 64 + ch * 8);
        }
        CP_COMMIT();
    };

#pragma unroll
    for (int r = 0; r < 4; r++) {
        int id = tid + r * 256;
        int row = id >> 3, ch = id & 7;
        CP16(Qb + row * LDHB + ch * 16, Qg + row * 64 + ch * 8);
    }
    CP_COMMIT();
    load_kv(0);
    load_kv(1);
    CP_WAIT(2);
    __syncthreads();

    uint32_t qf[4][4];
#pragma unroll
    for (int kt = 0; kt < 4; kt++)
        ldm_x4(qf[kt], Qb + (uint32_t)((warp * 16 + lr8) * LDHB + (kt * 16 + lc8) * 2));

    float m0 = -1e30f, m1 = -1e30f, l0 = 0.0f, l1 = 0.0f;
    float o[8][4];
#pragma unroll
    for (int nt = 0; nt < 8; nt++)
#pragma unroll
        for (int e = 0; e < 4; e++) o[nt][e] = 0.0f;

    const int NKB = SLEN / 64;
#pragma unroll 1
    for (int kb = 0; kb < NKB; kb++) {
        const uint32_t Kc = KV0 + (uint32_t)(kb % 3) * KVST;
        const uint32_t Vc = Kc + 64 * LDHB;
        if (kb + 2 < NKB) { load_kv(kb + 2); CP_WAIT(2); }
        else if (kb + 1 < NKB) { CP_WAIT(1); }
        else { CP_WAIT(0); }
        __syncthreads();

        float s[8][4];
#pragma unroll
        for (int nt = 0; nt < 8; nt++)
#pragma unroll
            for (int e = 0; e < 4; e++) s[nt][e] = 0.0f;
#pragma unroll
        for (int kt = 0; kt < 4; kt++)
#pragma unroll
            for (int p = 0; p < 4; p++) {
                uint32_t bk[4];
                ldm_x4(bk, Kc + (uint32_t)((p * 16 + lc8 + (lane & 7)) * LDHB
                                           + (kt * 16 + ((lane >> 3) & 1) * 8) * 2));
                mma_f16(s[2 * p],     qf[kt], &bk[0]);
                mma_f16(s[2 * p + 1], qf[kt], &bk[2]);
            }

        float mx0 = -1e30f, mx1 = -1e30f;
#pragma unroll
        for (int nt = 0; nt < 8; nt++) {
            mx0 = fmaxf(mx0, fmaxf(s[nt][0], s[nt][1]));
            mx1 = fmaxf(mx1, fmaxf(s[nt][2], s[nt][3]));
        }
        mx0 = fmaxf(mx0, __shfl_xor_sync(0xffffffffu, mx0, 1));
        mx0 = fmaxf(mx0, __shfl_xor_sync(0xffffffffu, mx0, 2));
        mx1 = fmaxf(mx1, __shfl_xor_sync(0xffffffffu, mx1, 1));
        mx1 = fmaxf(mx1, __shfl_xor_sync(0xffffffffu, mx1, 2));
        float mn0 = fmaxf(m0, mx0), mn1 = fmaxf(m1, mx1);
        float a0 = __expf(m0 - mn0), a1 = __expf(m1 - mn1);
        m0 = mn0; m1 = mn1;

        float sum0 = 0.0f, sum1 = 0.0f;
        uint32_t pf[4][4];
#pragma unroll
        for (int nt = 0; nt < 8; nt++) {
            float e0 = __expf(s[nt][0] - mn0), e1 = __expf(s[nt][1] - mn0);
            float e2 = __expf(s[nt][2] - mn1), e3 = __expf(s[nt][3] - mn1);
            sum0 += e0 + e1; sum1 += e2 + e3;
            uint32_t p01 = packh2(e0, e1), p23 = packh2(e2, e3);
            int kt = nt >> 1;
            if (nt & 1) { pf[kt][2] = p01; pf[kt][3] = p23; }
            else        { pf[kt][0] = p01; pf[kt][1] = p23; }
        }
        sum0 += __shfl_xor_sync(0xffffffffu, sum0, 1);
        sum0 += __shfl_xor_sync(0xffffffffu, sum0, 2);
        sum1 += __shfl_xor_sync(0xffffffffu, sum1, 1);
        sum1 += __shfl_xor_sync(0xffffffffu, sum1, 2);
        l0 = l0 * a0 + sum0;
        l1 = l1 * a1 + sum1;

#pragma unroll
        for (int nt = 0; nt < 8; nt++) {
            o[nt][0] *= a0; o[nt][1] *= a0;
            o[nt][2] *= a1; o[nt][3] *= a1;
        }
#pragma unroll
        for (int kt = 0; kt < 4; kt++)
#pragma unroll
            for (int p = 0; p < 4; p++) {
                uint32_t bv[4];
                ldm_x4t(bv, Vc + (uint32_t)((kt * 16 + lr8) * LDHB
                                            + (p * 16 + lc8) * 2));
                mma_f16(o[2 * p],     pf[kt], &bv[0]);
                mma_f16(o[2 * p + 1], pf[kt], &bv[2]);
            }
        __syncthreads();
    }

    const float i0 = 1.0f / l0, i1 = 1.0f / l1;
    const int b_ = bh >> 4, h = bh & 15;
    const int r0 = qblk * 128 + warp * 16 + g;
    const size_t tok0 = (size_t)b_ * SLEN + r0;
#pragma unroll
    for (int nt = 0; nt < 8; nt++) {
        int c = nt * 8 + 2 * t;
        *(uint32_t*)&O[tok0 * EMBED + h * 64 + c] =
            packh2(o[nt][0] * i0, o[nt][1] * i0);
        *(uint32_t*)&O[(tok0 + 8) * EMBED + h * 64 + c] =
            packh2(o[nt][2] * i1, o[nt][3] * i1);
    }
}

// ---------------------------------------------------------------------------
extern "C" void kernel_launch(void* const* d_in, const int* in_sizes, int n_in,
                              void* d_out, int out_size)
{
    const float* x    = (const float*)d_in[0];
    const float* Wqkv = (const float*)d_in[1];
    const float* Wout = (const float*)d_in[2];
    float* out = (float*)d_out;

    __half *Qp, *Kp, *Vp, *xh, *xl, *op, *w1, *w2;
    cudaGetSymbolAddress((void**)&Qp, g_Q);
    cudaGetSymbolAddress((void**)&Kp, g_K);
    cudaGetSymbolAddress((void**)&Vp, g_V);
    cudaGetSymbolAddress((void**)&xh, g_xh);  cudaGetSymbolAddress((void**)&xl, g_xl);
    cudaGetSymbolAddress((void**)&op, g_o);
    cudaGetSymbolAddress((void**)&w1, g_w1);  cudaGetSymbolAddress((void**)&w2, g_w2);

    const int smem2 = 3 * (36864 + 17408);   // TERMS=2: 162816
    const int smem1 = 3 * (18432 + 17408);   // TERMS=1: 107520
    static bool configured = false;
    if (!configured) {
        cudaFuncSetAttribute(attn_reg,
                             cudaFuncAttributeMaxDynamicSharedMemorySize, ATTN_SMEM);
        cudaFuncSetAttribute(gemm_f16<0, 2>,
                             cudaFuncAttributeMaxDynamicSharedMemorySize, smem2);
        cudaFuncSetAttribute(gemm_f16<1, 1>,
                             cudaFuncAttributeMaxDynamicSharedMemorySize, smem1);
        configured = true;
    }

    // 0) conversions
    int n4x = NTOK * EMBED / 4, n4q = EMBED * QKVN / 4, n4o = EMBED * EMBED / 4;
    conv_split16<<<(n4x + 255) / 256, 256>>>(x, xh, xl, n4x);
    conv_h<<<(n4q + 255) / 256, 256>>>(Wqkv, w1, n4q);
    conv_h<<<(n4o + 255) / 256, 256>>>(Wout, w2, n4o);

    // 1) QKV projection (2-term) -> fp16 Q(scaled)/K/V
    dim3 g1(QKVN / 128, NTOK / 128);
    gemm_f16<0, 2><<<g1, 256, smem2>>>(xh, xl, w1, nullptr, Qp, Kp, Vp,
                                       NTOK, QKVN, EMBED);

    // 2) register FA2 -> fp16 O
    dim3 g2(SLEN / 128, BATCH * NHEAD);
    attn_reg<<<g2, 256, ATTN_SMEM>>>(Qp, Kp, Vp, op);

    // 3) output projection (1-term)
    dim3 g3(EMBED / 128, NTOK / 128);
    gemm_f16<1, 1><<<g3, 256, smem1>>>(op, nullptr, w2, out, nullptr, nullptr, nullptr,
                                       NTOK, EMBED, EMBED);
}

// round 10
// speedup vs baseline: 1.0847x; 1.0847x over previous
#include <cuda_runtime.h>
#include <cuda_fp16.h>
#include <stdint.h>
#include <math.h>

#define BATCH 4
#define SLEN  2048
#define EMBED 1024
#define NHEAD 16
#define HDIM  64
#define NTOK  (BATCH * SLEN)     // 8192
#define QKVN  (3 * EMBED)        // 3072

__device__ __half g_Q[(size_t)BATCH * NHEAD * SLEN * HDIM];   // pre-scaled by 1/32
__device__ __half g_K[(size_t)BATCH * NHEAD * SLEN * HDIM];
__device__ __half g_V[(size_t)BATCH * NHEAD * SLEN * HDIM];
__device__ __half g_xh[(size_t)NTOK * EMBED], g_xl[(size_t)NTOK * EMBED];
__device__ __half g_o[(size_t)NTOK * EMBED];
__device__ __half g_w1[(size_t)EMBED * QKVN];
__device__ __half g_w2[(size_t)EMBED * EMBED];

// ------------------------------ helpers ------------------------------------
__device__ __forceinline__ uint32_t s2u(const void* p) {
    uint32_t a;
    asm("{ .reg .u64 t; cvta.to.shared.u64 t, %1; cvt.u32.u64 %0, t; }" : "=r"(a) : "l"(p));
    return a;
}
__device__ __forceinline__ void mma_f16(float* d, const uint32_t* a, const uint32_t* b) {
    asm volatile("mma.sync.aligned.m16n8k16.row.col.f32.f16.f16.f32 "
        "{%0,%1,%2,%3},{%4,%5,%6,%7},{%8,%9},{%0,%1,%2,%3};"
        : "+f"(d[0]), "+f"(d[1]), "+f"(d[2]), "+f"(d[3])
        : "r"(a[0]), "r"(a[1]), "r"(a[2]), "r"(a[3]), "r"(b[0]), "r"(b[1]));
}
__device__ __forceinline__ void ldm_x4(uint32_t* r, uint32_t a) {
    asm volatile("ldmatrix.sync.aligned.m8n8.x4.shared.b16 {%0,%1,%2,%3},[%4];"
        : "=r"(r[0]), "=r"(r[1]), "=r"(r[2]), "=r"(r[3]) : "r"(a));
}
__device__ __forceinline__ void ldm_x4t(uint32_t* r, uint32_t a) {
    asm volatile("ldmatrix.sync.aligned.m8n8.x4.trans.shared.b16 {%0,%1,%2,%3},[%4];"
        : "=r"(r[0]), "=r"(r[1]), "=r"(r[2]), "=r"(r[3]) : "r"(a));
}
__device__ __forceinline__ uint32_t packh2(float a, float b) {
    __half2 h = __floats2half2_rn(a, b);
    return *(uint32_t*)&h;
}
__device__ __forceinline__ void split2h(float a, float b, uint32_t& hi, uint32_t& lo) {
    __half ha = __float2half_rn(a), hb = __float2half_rn(b);
    hi = (uint32_t)__half_as_ushort(ha) | ((uint32_t)__half_as_ushort(hb) << 16);
    lo = packh2(a - __half2float(ha), b - __half2float(hb));
}
#define CP16(sa, gp) \
    asm volatile("cp.async.cg.shared.global [%0], [%1], 16;" :: "r"(sa), "l"(gp) : "memory")
#define CP_COMMIT()  asm volatile("cp.async.commit_group;" ::: "memory")
#define CP_WAIT(n)   asm volatile("cp.async.wait_group %0;" :: "n"(n) : "memory")

// ------------------------- conversion kernels ------------------------------
__global__ void __launch_bounds__(256)
conv_split16(const float* __restrict__ X, __half* __restrict__ Xh,
             __half* __restrict__ Xl, int n4)
{
    int i = blockIdx.x * blockDim.x + threadIdx.x;
    if (i >= n4) return;
    float4 v = ((const float4*)X)[i];
    uint32_t h0, l0, h1, l1;
    split2h(v.x, v.y, h0, l0);
    split2h(v.z, v.w, h1, l1);
    ((uint2*)Xh)[i] = make_uint2(h0, h1);
    ((uint2*)Xl)[i] = make_uint2(l0, l1);
}
__global__ void __launch_bounds__(256)
conv_h(const float* __restrict__ X, __half* __restrict__ Y, int n4)
{
    int i = blockIdx.x * blockDim.x + threadIdx.x;
    if (i >= n4) return;
    float4 v = ((const float4*)X)[i];
    ((uint2*)Y)[i] = make_uint2(packh2(v.x, v.y), packh2(v.z, v.w));
}

// ---------------------------------------------------------------------------
// fp16 GEMM, TERMS-term A (hi[+lo]), BK=32, 3-stage cp.async pipeline,
// SINGLE __syncthreads per iteration (multistage ordering).
// 256 thr, 8 warps 2x4 (warp 64x32).
// MODE 0: de-interleave epilogue -> fp16 Q(scaled)/K/V.  MODE 1: fp32 store.
// ---------------------------------------------------------------------------
#define OFS_AL 10240

template <int MODE, int TERMS>
__global__ void __launch_bounds__(256, 2)
gemm_f16(const __half* __restrict__ Ah, const __half* __restrict__ Al,
         const __half* __restrict__ B, float* __restrict__ C,
         __half* __restrict__ Qo, __half* __restrict__ Ko, __half* __restrict__ Vo,
         int M, int N, int K)
{
    constexpr uint32_t OFSB = (TERMS == 2) ? 20480u : 10240u;
    constexpr uint32_t STGB = (TERMS == 2) ? 29696u : 19456u;

    extern __shared__ char gsm[];
    const uint32_t smb = s2u(gsm);

    const int tid = threadIdx.x, lane = tid & 31, warp = tid >> 5;
    const int wm = warp >> 2, wn = warp & 3;
    const int g = lane >> 2, t = lane & 3;
    const int m0 = blockIdx.y * 128, n0 = blockIdx.x * 128;

    const int arow = wm * 64 + (lane & 7) + ((lane >> 3) & 1) * 8;
    const int acol = (lane >> 4) * 8;
    const int brow = (lane & 7) + ((lane >> 3) & 1) * 8;
    const int bcol = (lane >> 4) * 8;

    float acc[4][4][4];
#pragma unroll
    for (int mt = 0; mt < 4; mt++)
#pragma unroll
        for (int nt = 0; nt < 4; nt++)
#pragma unroll
            for (int e = 0; e < 4; e++) acc[mt][nt][e] = 0.0f;

    const int KIT = K / 32;

    auto load_stage = [&](int it) {
        const uint32_t base = smb + (uint32_t)(it % 3) * STGB;
        const int k0 = it * 32;
#pragma unroll
        for (int r = 0; r < 2; r++) {
            int id = tid + r * 256;
            int row = id >> 2, cc = id & 3;
            uint32_t da = base + (uint32_t)(row * 80 + cc * 16);
            size_t ga = (size_t)(m0 + row) * K + k0 + cc * 8;
            CP16(da, Ah + ga);
            if (TERMS == 2) CP16(da + OFS_AL, Al + ga);
            int br = id >> 4, bc = id & 15;
            CP16(base + OFSB + (uint32_t)(br * 272 + bc * 16),
                 B + (size_t)(k0 + br) * N + n0 + bc * 8);
        }
        CP_COMMIT();
    };

    load_stage(0);
    load_stage(1);

#pragma unroll 1
    for (int it = 0; it < KIT; it++) {
        const uint32_t cur = smb + (uint32_t)(it % 3) * STGB;
        if (it + 1 < KIT) { CP_WAIT(1); } else { CP_WAIT(0); }
        __syncthreads();                 // all warps done reading stage it-1
        if (it + 2 < KIT) load_stage(it + 2);   // overwrites (it-1)%3: safe

#pragma unroll
        for (int ks = 0; ks < 2; ks++) {
            uint32_t ah[4][4], al[4][4];
#pragma unroll
            for (int mt = 0; mt < 4; mt++) {
                uint32_t ad = cur + (uint32_t)(((arow + mt * 16) * 40 + acol + ks * 16) * 2);
                ldm_x4(ah[mt], ad);
                if (TERMS == 2) ldm_x4(al[mt], ad + OFS_AL);
            }
            uint32_t bb[2][4];
#pragma unroll
            for (int p = 0; p < 2; p++)
                ldm_x4t(bb[p], cur + OFSB
                        + (uint32_t)((ks * 16 + brow) * 272
                                     + (wn * 32 + p * 16 + bcol) * 2));
#pragma unroll
            for (int p = 0; p < 2; p++)
#pragma unroll
                for (int sub = 0; sub < 2; sub++) {
                    const int nt = 2 * p + sub;
#pragma unroll
                    for (int mt = 0; mt < 4; mt++) {
                        mma_f16(acc[mt][nt], ah[mt], &bb[p][sub * 2]);
                        if (TERMS == 2) mma_f16(acc[mt][nt], al[mt], &bb[p][sub * 2]);
                    }
                }
        }
    }

    if (MODE == 0) {
#pragma unroll
        for (int mt = 0; mt < 4; mt++)
#pragma unroll
            for (int nt = 0; nt < 4; nt++) {
                int r0 = m0 + wm * 64 + mt * 16 + g;
                int c0 = n0 + wn * 32 + nt * 8 + 2 * t;
#pragma unroll
                for (int e = 0; e < 4; e++) {
                    int row = r0 + (e >> 1) * 8;
                    int col = c0 + (e & 1);
                    int b_ = row >> 11, s = row & 2047;
                    int h = col / 192;
                    int rem = col - h * 192;
                    int d = rem / 3, w = rem - 3 * d;
                    __half* dst = (w == 0) ? Qo : (w == 1) ? Ko : Vo;
                    float sc = (w == 0) ? 0.03125f : 1.0f;
                    dst[(((size_t)b_ * NHEAD + h) * SLEN + s) * HDIM + d] =
                        __float2half_rn(acc[mt][nt][e] * sc);
                }
            }
    } else {
#pragma unroll
        for (int mt = 0; mt < 4; mt++)
#pragma unroll
            for (int nt = 0; nt < 4; nt++) {
                size_t r = (size_t)(m0 + wm * 64 + mt * 16 + g);
                int    c = n0 + wn * 32 + nt * 8 + 2 * t;
                *(float2*)&C[r * N + c]       = make_float2(acc[mt][nt][0], acc[mt][nt][1]);
                *(float2*)&C[(r + 8) * N + c] = make_float2(acc[mt][nt][2], acc[mt][nt][3]);
            }
    }
}

// ---------------------------------------------------------------------------
// Register FA2: BQ=128 (8 warps x 16 rows), BKEY=64, D=64.
// K/V 3-stage cp.async pipeline, single barrier per iteration.
// ---------------------------------------------------------------------------
#define LDHB 144
#define KVST (2 * 64 * LDHB)
#define ATTN_SMEM (128 * LDHB + 3 * KVST)

__global__ void __launch_bounds__(256, 2)
attn_reg(const __half* __restrict__ Q, const __half* __restrict__ K,
         const __half* __restrict__ V, __half* __restrict__ O)
{
    extern __shared__ char smc[];
    const uint32_t Qb = s2u(smc);
    const uint32_t KV0 = Qb + 128 * LDHB;

    const int tid = threadIdx.x, lane = tid & 31, warp = tid >> 5;
    const int g = lane >> 2, t = lane & 3;
    const int lr8 = (lane & 7) + ((lane >> 3) & 1) * 8;
    const int lc8 = (lane >> 4) * 8;
    const int qblk = blockIdx.x, bh = blockIdx.y;

    const __half* Qg = Q + ((size_t)bh * SLEN + qblk * 128) * HDIM;
    const __half* Kg = K + (size_t)bh * SLEN * HDIM;
    const __half* Vg = V + (size_t)bh * SLEN * HDIM;

    auto load_kv = [&](int kb) {
        const uint32_t base = KV0 + (uint32_t)(kb % 3) * KVST;
        const __half* Kgb = Kg + (size_t)kb * 64 * HDIM;
        const __half* Vgb = Vg + (size_t)kb * 64 * HDIM;
#pragma unroll
        for (int r = 0; r < 2; r++) {
            int id = tid + r * 256;
            int row = id >> 3, ch = id & 7;
            CP16(base + row * LDHB + ch * 16, Kgb + row * 64 + ch * 8);
            CP16(base + 64 * LDHB + row * LDHB + ch * 16, Vgb + row * 64 + ch * 8);
        }
        CP_COMMIT();
    };

#pragma unroll
    for (int r = 0; r < 4; r++) {
        int id = tid + r * 256;
        int row = id >> 3, ch = id & 7;
        CP16(Qb + row * LDHB + ch * 16, Qg + row * 64 + ch * 8);
    }
    CP_COMMIT();
    load_kv(0);
    load_kv(1);
    CP_WAIT(2);             // Q resident
    __syncthreads();

    uint32_t qf[4][4];
#pragma unroll
    for (int kt = 0; kt < 4; kt++)
        ldm_x4(qf[kt], Qb + (uint32_t)((warp * 16 + lr8) * LDHB + (kt * 16 + lc8) * 2));

    float m0 = -1e30f, m1 = -1e30f, l0 = 0.0f, l1 = 0.0f;
    float o[8][4];
#pragma unroll
    for (int nt = 0; nt < 8; nt++)
#pragma unroll
        for (int e = 0; e < 4; e++) o[nt][e] = 0.0f;

    const int NKB = SLEN / 64;
#pragma unroll 1
    for (int kb = 0; kb < NKB; kb++) {
        const uint32_t Kc = KV0 + (uint32_t)(kb % 3) * KVST;
        const uint32_t Vc = Kc + 64 * LDHB;
        if (kb + 1 < NKB) { CP_WAIT(1); } else { CP_WAIT(0); }
        __syncthreads();                     // all warps done with kb-1
        if (kb + 2 < NKB) load_kv(kb + 2);   // overwrites (kb-1)%3: safe

        float s[8][4];
#pragma unroll
        for (int nt = 0; nt < 8; nt++)
#pragma unroll
            for (int e = 0; e < 4; e++) s[nt][e] = 0.0f;
#pragma unroll
        for (int kt = 0; kt < 4; kt++)
#pragma unroll
            for (int p = 0; p < 4; p++) {
                uint32_t bk[4];
                ldm_x4(bk, Kc + (uint32_t)((p * 16 + lc8 + (lane & 7)) * LDHB
                                           + (kt * 16 + ((lane >> 3) & 1) * 8) * 2));
                mma_f16(s[2 * p],     qf[kt], &bk[0]);
                mma_f16(s[2 * p + 1], qf[kt], &bk[2]);
            }

        float mx0 = -1e30f, mx1 = -1e30f;
#pragma unroll
        for (int nt = 0; nt < 8; nt++) {
            mx0 = fmaxf(mx0, fmaxf(s[nt][0], s[nt][1]));
            mx1 = fmaxf(mx1, fmaxf(s[nt][2], s[nt][3]));
        }
        mx0 = fmaxf(mx0, __shfl_xor_sync(0xffffffffu, mx0, 1));
        mx0 = fmaxf(mx0, __shfl_xor_sync(0xffffffffu, mx0, 2));
        mx1 = fmaxf(mx1, __shfl_xor_sync(0xffffffffu, mx1, 1));
        mx1 = fmaxf(mx1, __shfl_xor_sync(0xffffffffu, mx1, 2));
        float mn0 = fmaxf(m0, mx0), mn1 = fmaxf(m1, mx1);
        float a0 = __expf(m0 - mn0), a1 = __expf(m1 - mn1);
        m0 = mn0; m1 = mn1;

        float sum0 = 0.0f, sum1 = 0.0f;
        uint32_t pf[4][4];
#pragma unroll
        for (int nt = 0; nt < 8; nt++) {
            float e0 = __expf(s[nt][0] - mn0), e1 = __expf(s[nt][1] - mn0);
            float e2 = __expf(s[nt][2] - mn1), e3 = __expf(s[nt][3] - mn1);
            sum0 += e0 + e1; sum1 += e2 + e3;
            uint32_t p01 = packh2(e0, e1), p23 = packh2(e2, e3);
            int kt = nt >> 1;
            if (nt & 1) { pf[kt][2] = p01; pf[kt][3] = p23; }
            else        { pf[kt][0] = p01; pf[kt][1] = p23; }
        }
        sum0 += __shfl_xor_sync(0xffffffffu, sum0, 1);
        sum0 += __shfl_xor_sync(0xffffffffu, sum0, 2);
        sum1 += __shfl_xor_sync(0xffffffffu, sum1, 1);
        sum1 += __shfl_xor_sync(0xffffffffu, sum1, 2);
        l0 = l0 * a0 + sum0;
        l1 = l1 * a1 + sum1;

#pragma unroll
        for (int nt = 0; nt < 8; nt++) {
            o[nt][0] *= a0; o[nt][1] *= a0;
            o[nt][2] *= a1; o[nt][3] *= a1;
        }
#pragma unroll
        for (int kt = 0; kt < 4; kt++)
#pragma unroll
            for (int p = 0; p < 4; p++) {
                uint32_t bv[4];
                ldm_x4t(bv, Vc + (uint32_t)((kt * 16 + lr8) * LDHB
                                            + (p * 16 + lc8) * 2));
                mma_f16(o[2 * p],     pf[kt], &bv[0]);
                mma_f16(o[2 * p + 1], pf[kt], &bv[2]);
            }
    }

    const float i0 = 1.0f / l0, i1 = 1.0f / l1;
    const int b_ = bh >> 4, h = bh & 15;
    const int r0 = qblk * 128 + warp * 16 + g;
    const size_t tok0 = (size_t)b_ * SLEN + r0;
#pragma unroll
    for (int nt = 0; nt < 8; nt++) {
        int c = nt * 8 + 2 * t;
        *(uint32_t*)&O[tok0 * EMBED + h * 64 + c] =
            packh2(o[nt][0] * i0, o[nt][1] * i0);
        *(uint32_t*)&O[(tok0 + 8) * EMBED + h * 64 + c] =
            packh2(o[nt][2] * i1, o[nt][3] * i1);
    }
}

// ---------------------------------------------------------------------------
extern "C" void kernel_launch(void* const* d_in, const int* in_sizes, int n_in,
                              void* d_out, int out_size)
{
    const float* x    = (const float*)d_in[0];
    const float* Wqkv = (const float*)d_in[1];
    const float* Wout = (const float*)d_in[2];
    float* out = (float*)d_out;

    __half *Qp, *Kp, *Vp, *xh, *xl, *op, *w1, *w2;
    cudaGetSymbolAddress((void**)&Qp, g_Q);
    cudaGetSymbolAddress((void**)&Kp, g_K);
    cudaGetSymbolAddress((void**)&Vp, g_V);
    cudaGetSymbolAddress((void**)&xh, g_xh);  cudaGetSymbolAddress((void**)&xl, g_xl);
    cudaGetSymbolAddress((void**)&op, g_o);
    cudaGetSymbolAddress((void**)&w1, g_w1);  cudaGetSymbolAddress((void**)&w2, g_w2);

    const int smem2 = 3 * 29696;   // TERMS=2
    const int smem1 = 3 * 19456;   // TERMS=1
    static bool configured = false;
    if (!configured) {
        cudaFuncSetAttribute(attn_reg,
                             cudaFuncAttributeMaxDynamicSharedMemorySize, ATTN_SMEM);
        cudaFuncSetAttribute(gemm_f16<0, 2>,
                             cudaFuncAttributeMaxDynamicSharedMemorySize, smem2);
        cudaFuncSetAttribute(gemm_f16<1, 1>,
                             cudaFuncAttributeMaxDynamicSharedMemorySize, smem1);
        configured = true;
    }

    // 0) conversions
    int n4x = NTOK * EMBED / 4, n4q = EMBED * QKVN / 4, n4o = EMBED * EMBED / 4;
    conv_split16<<<(n4x + 255) / 256, 256>>>(x, xh, xl, n4x);
    conv_h<<<(n4q + 255) / 256, 256>>>(Wqkv, w1, n4q);
    conv_h<<<(n4o + 255) / 256, 256>>>(Wout, w2, n4o);

    // 1) QKV projection (2-term) -> fp16 Q(scaled)/K/V
    dim3 g1(QKVN / 128, NTOK / 128);
    gemm_f16<0, 2><<<g1, 256, smem2>>>(xh, xl, w1, nullptr, Qp, Kp, Vp,
                                       NTOK, QKVN, EMBED);

    // 2) register FA2 -> fp16 O
    dim3 g2(SLEN / 128, BATCH * NHEAD);
    attn_reg<<<g2, 256, ATTN_SMEM>>>(Qp, Kp, Vp, op);

    // 3) output projection (1-term)
    dim3 g3(EMBED / 128, NTOK / 128);
    gemm_f16<1, 1><<<g3, 256, smem1>>>(op, nullptr, w2, out, nullptr, nullptr, nullptr,
                                       NTOK, EMBED, EMBED);
}

// round 11
// speedup vs baseline: 1.3053x; 1.2034x over previous
#include <cuda_runtime.h>
#include <cuda_fp16.h>
#include <stdint.h>
#include <math.h>

#define BATCH 4
#define SLEN  2048
#define EMBED 1024
#define NHEAD 16
#define HDIM  64
#define NTOK  (BATCH * SLEN)     // 8192
#define QKVN  (3 * EMBED)        // 3072

__device__ __half g_Q[(size_t)BATCH * NHEAD * SLEN * HDIM];   // pre-scaled by 1/32
__device__ __half g_K[(size_t)BATCH * NHEAD * SLEN * HDIM];
__device__ __half g_V[(size_t)BATCH * NHEAD * SLEN * HDIM];
__device__ __half g_x[(size_t)NTOK * EMBED];
__device__ __half g_o[(size_t)NTOK * EMBED];
__device__ __half g_w1[(size_t)EMBED * QKVN];
__device__ __half g_w2[(size_t)EMBED * EMBED];

// ------------------------------ helpers ------------------------------------
__device__ __forceinline__ uint32_t s2u(const void* p) {
    uint32_t a;
    asm("{ .reg .u64 t; cvta.to.shared.u64 t, %1; cvt.u32.u64 %0, t; }" : "=r"(a) : "l"(p));
    return a;
}
__device__ __forceinline__ void mma_f16(float* d, const uint32_t* a, const uint32_t* b) {
    asm volatile("mma.sync.aligned.m16n8k16.row.col.f32.f16.f16.f32 "
        "{%0,%1,%2,%3},{%4,%5,%6,%7},{%8,%9},{%0,%1,%2,%3};"
        : "+f"(d[0]), "+f"(d[1]), "+f"(d[2]), "+f"(d[3])
        : "r"(a[0]), "r"(a[1]), "r"(a[2]), "r"(a[3]), "r"(b[0]), "r"(b[1]));
}
__device__ __forceinline__ void ldm_x4(uint32_t* r, uint32_t a) {
    asm volatile("ldmatrix.sync.aligned.m8n8.x4.shared.b16 {%0,%1,%2,%3},[%4];"
        : "=r"(r[0]), "=r"(r[1]), "=r"(r[2]), "=r"(r[3]) : "r"(a));
}
__device__ __forceinline__ void ldm_x4t(uint32_t* r, uint32_t a) {
    asm volatile("ldmatrix.sync.aligned.m8n8.x4.trans.shared.b16 {%0,%1,%2,%3},[%4];"
        : "=r"(r[0]), "=r"(r[1]), "=r"(r[2]), "=r"(r[3]) : "r"(a));
}
__device__ __forceinline__ uint32_t packh2(float a, float b) {
    __half2 h = __floats2half2_rn(a, b);
    return *(uint32_t*)&h;
}
#define CP16(sa, gp) \
    asm volatile("cp.async.cg.shared.global [%0], [%1], 16;" :: "r"(sa), "l"(gp) : "memory")
#define CP_COMMIT()  asm volatile("cp.async.commit_group;" ::: "memory")
#define CP_WAIT(n)   asm volatile("cp.async.wait_group %0;" :: "n"(n) : "memory")

// ------------------------- conversion kernel -------------------------------
__global__ void __launch_bounds__(256)
conv_h(const float* __restrict__ X, __half* __restrict__ Y, int n4)
{
    int i = blockIdx.x * blockDim.x + threadIdx.x;
    if (i >= n4) return;
    float4 v = ((const float4*)X)[i];
    ((uint2*)Y)[i] = make_uint2(packh2(v.x, v.y), packh2(v.z, v.w));
}

// ---------------------------------------------------------------------------
// fp16 GEMM: C = A@B (both fp16). BM=BN=128, BK=32, 4-stage cp.async
// pipeline, single barrier per iteration. 256 thr, 8 warps 2x4 (warp 64x32).
// MODE 0: de-interleave epilogue -> fp16 Q(scaled)/K/V.  MODE 1: fp32 store.
// ---------------------------------------------------------------------------
#define OFSB 10240u
#define STGB 19456u
#define GEMM_SMEM (4 * 19456)

template <int MODE>
__global__ void __launch_bounds__(256, 2)
gemm_f16(const __half* __restrict__ A, const __half* __restrict__ B,
         float* __restrict__ C,
         __half* __restrict__ Qo, __half* __restrict__ Ko, __half* __restrict__ Vo,
         int M, int N, int K)
{
    extern __shared__ char gsm[];
    const uint32_t smb = s2u(gsm);

    const int tid = threadIdx.x, lane = tid & 31, warp = tid >> 5;
    const int wm = warp >> 2, wn = warp & 3;
    const int g = lane >> 2, t = lane & 3;
    const int m0 = blockIdx.y * 128, n0 = blockIdx.x * 128;

    const int arow = wm * 64 + (lane & 7) + ((lane >> 3) & 1) * 8;
    const int acol = (lane >> 4) * 8;
    const int brow = (lane & 7) + ((lane >> 3) & 1) * 8;
    const int bcol = (lane >> 4) * 8;

    float acc[4][4][4];
#pragma unroll
    for (int mt = 0; mt < 4; mt++)
#pragma unroll
        for (int nt = 0; nt < 4; nt++)
#pragma unroll
            for (int e = 0; e < 4; e++) acc[mt][nt][e] = 0.0f;

    const int KIT = K / 32;

    auto load_stage = [&](int it) {
        const uint32_t base = smb + (uint32_t)(it & 3) * STGB;
        const int k0 = it * 32;
#pragma unroll
        for (int r = 0; r < 2; r++) {
            int id = tid + r * 256;
            int row = id >> 2, cc = id & 3;
            CP16(base + (uint32_t)(row * 80 + cc * 16),
                 A + (size_t)(m0 + row) * K + k0 + cc * 8);
            int br = id >> 4, bc = id & 15;
            CP16(base + OFSB + (uint32_t)(br * 272 + bc * 16),
                 B + (size_t)(k0 + br) * N + n0 + bc * 8);
        }
        CP_COMMIT();
    };

    load_stage(0);
    load_stage(1);
    load_stage(2);

#pragma unroll 1
    for (int it = 0; it < KIT; it++) {
        const uint32_t cur = smb + (uint32_t)(it & 3) * STGB;
        if (it + 2 < KIT) { CP_WAIT(2); }
        else if (it + 1 < KIT) { CP_WAIT(1); }
        else { CP_WAIT(0); }
        __syncthreads();                        // all warps done reading it-1
        if (it + 3 < KIT) load_stage(it + 3);   // overwrites (it-1)&3: safe

#pragma unroll
        for (int ks = 0; ks < 2; ks++) {
            uint32_t ah[4][4];
#pragma unroll
            for (int mt = 0; mt < 4; mt++)
                ldm_x4(ah[mt], cur + (uint32_t)(((arow + mt * 16) * 40 + acol + ks * 16) * 2));
            uint32_t bb[2][4];
#pragma unroll
            for (int p = 0; p < 2; p++)
                ldm_x4t(bb[p], cur + OFSB
                        + (uint32_t)((ks * 16 + brow) * 272
                                     + (wn * 32 + p * 16 + bcol) * 2));
#pragma unroll
            for (int p = 0; p < 2; p++)
#pragma unroll
                for (int sub = 0; sub < 2; sub++) {
                    const int nt = 2 * p + sub;
#pragma unroll
                    for (int mt = 0; mt < 4; mt++)
                        mma_f16(acc[mt][nt], ah[mt], &bb[p][sub * 2]);
                }
        }
    }

    if (MODE == 0) {
#pragma unroll
        for (int mt = 0; mt < 4; mt++)
#pragma unroll
            for (int nt = 0; nt < 4; nt++) {
                int r0 = m0 + wm * 64 + mt * 16 + g;
                int c0 = n0 + wn * 32 + nt * 8 + 2 * t;
#pragma unroll
                for (int e = 0; e < 4; e++) {
                    int row = r0 + (e >> 1) * 8;
                    int col = c0 + (e & 1);
                    int b_ = row >> 11, s = row & 2047;
                    int h = col / 192;
                    int rem = col - h * 192;
                    int d = rem / 3, w = rem - 3 * d;
                    __half* dst = (w == 0) ? Qo : (w == 1) ? Ko : Vo;
                    float sc = (w == 0) ? 0.03125f : 1.0f;
                    dst[(((size_t)b_ * NHEAD + h) * SLEN + s) * HDIM + d] =
                        __float2half_rn(acc[mt][nt][e] * sc);
                }
            }
    } else {
#pragma unroll
        for (int mt = 0; mt < 4; mt++)
#pragma unroll
            for (int nt = 0; nt < 4; nt++) {
                size_t r = (size_t)(m0 + wm * 64 + mt * 16 + g);
                int    c = n0 + wn * 32 + nt * 8 + 2 * t;
                *(float2*)&C[r * N + c]       = make_float2(acc[mt][nt][0], acc[mt][nt][1]);
                *(float2*)&C[(r + 8) * N + c] = make_float2(acc[mt][nt][2], acc[mt][nt][3]);
            }
    }
}

// ---------------------------------------------------------------------------
// Register FA2: BQ=128 (8 warps x 16 rows), BKEY=64, D=64.
// K/V 3-stage cp.async pipeline, single barrier per iteration.
// ---------------------------------------------------------------------------
#define LDHB 144
#define KVST (2 * 64 * LDHB)
#define ATTN_SMEM (128 * LDHB + 3 * KVST)

__global__ void __launch_bounds__(256, 2)
attn_reg(const __half* __restrict__ Q, const __half* __restrict__ K,
         const __half* __restrict__ V, __half* __restrict__ O)
{
    extern __shared__ char smc[];
    const uint32_t Qb = s2u(smc);
    const uint32_t KV0 = Qb + 128 * LDHB;

    const int tid = threadIdx.x, lane = tid & 31, warp = tid >> 5;
    const int g = lane >> 2, t = lane & 3;
    const int lr8 = (lane & 7) + ((lane >> 3) & 1) * 8;
    const int lc8 = (lane >> 4) * 8;
    const int qblk = blockIdx.x, bh = blockIdx.y;

    const __half* Qg = Q + ((size_t)bh * SLEN + qblk * 128) * HDIM;
    const __half* Kg = K + (size_t)bh * SLEN * HDIM;
    const __half* Vg = V + (size_t)bh * SLEN * HDIM;

    auto load_kv = [&](int kb) {
        const uint32_t base = KV0 + (uint32_t)(kb % 3) * KVST;
        const __half* Kgb = Kg + (size_t)kb * 64 * HDIM;
        const __half* Vgb = Vg + (size_t)kb * 64 * HDIM;
#pragma unroll
        for (int r = 0; r < 2; r++) {
            int id = tid + r * 256;
            int row = id >> 3, ch = id & 7;
            CP16(base + row * LDHB + ch * 16, Kgb + row * 64 + ch * 8);
            CP16(base + 64 * LDHB + row * LDHB + ch * 16, Vgb + row * 64 + ch * 8);
        }
        CP_COMMIT();
    };

#pragma unroll
    for (int r = 0; r < 4; r++) {
        int id = tid + r * 256;
        int row = id >> 3, ch = id & 7;
        CP16(Qb + row * LDHB + ch * 16, Qg + row * 64 + ch * 8);
    }
    CP_COMMIT();
    load_kv(0);
    load_kv(1);
    CP_WAIT(2);             // Q resident
    __syncthreads();

    uint32_t qf[4][4];
#pragma unroll
    for (int kt = 0; kt < 4; kt++)
        ldm_x4(qf[kt], Qb + (uint32_t)((warp * 16 + lr8) * LDHB + (kt * 16 + lc8) * 2));

    float m0 = -1e30f, m1 = -1e30f, l0 = 0.0f, l1 = 0.0f;
    float o[8][4];
#pragma unroll
    for (int nt = 0; nt < 8; nt++)
#pragma unroll
        for (int e = 0; e < 4; e++) o[nt][e] = 0.0f;

    const int NKB = SLEN / 64;
#pragma unroll 1
    for (int kb = 0; kb < NKB; kb++) {
        const uint32_t Kc = KV0 + (uint32_t)(kb % 3) * KVST;
        const uint32_t Vc = Kc + 64 * LDHB;
        if (kb + 1 < NKB) { CP_WAIT(1); } else { CP_WAIT(0); }
        __syncthreads();
        if (kb + 2 < NKB) load_kv(kb + 2);

        float s[8][4];
#pragma unroll
        for (int nt = 0; nt < 8; nt++)
#pragma unroll
            for (int e = 0; e < 4; e++) s[nt][e] = 0.0f;
#pragma unroll
        for (int kt = 0; kt < 4; kt++)
#pragma unroll
            for (int p = 0; p < 4; p++) {
                uint32_t bk[4];
                ldm_x4(bk, Kc + (uint32_t)((p * 16 + lc8 + (lane & 7)) * LDHB
                                           + (kt * 16 + ((lane >> 3) & 1) * 8) * 2));
                mma_f16(s[2 * p],     qf[kt], &bk[0]);
                mma_f16(s[2 * p + 1], qf[kt], &bk[2]);
            }

        float mx0 = -1e30f, mx1 = -1e30f;
#pragma unroll
        for (int nt = 0; nt < 8; nt++) {
            mx0 = fmaxf(mx0, fmaxf(s[nt][0], s[nt][1]));
            mx1 = fmaxf(mx1, fmaxf(s[nt][2], s[nt][3]));
        }
        mx0 = fmaxf(mx0, __shfl_xor_sync(0xffffffffu, mx0, 1));
        mx0 = fmaxf(mx0, __shfl_xor_sync(0xffffffffu, mx0, 2));
        mx1 = fmaxf(mx1, __shfl_xor_sync(0xffffffffu, mx1, 1));
        mx1 = fmaxf(mx1, __shfl_xor_sync(0xffffffffu, mx1, 2));
        float mn0 = fmaxf(m0, mx0), mn1 = fmaxf(m1, mx1);
        float a0 = __expf(m0 - mn0), a1 = __expf(m1 - mn1);
        m0 = mn0; m1 = mn1;

        float sum0 = 0.0f, sum1 = 0.0f;
        uint32_t pf[4][4];
#pragma unroll
        for (int nt = 0; nt < 8; nt++) {
            float e0 = __expf(s[nt][0] - mn0), e1 = __expf(s[nt][1] - mn0);
            float e2 = __expf(s[nt][2] - mn1), e3 = __expf(s[nt][3] - mn1);
            sum0 += e0 + e1; sum1 += e2 + e3;
            uint32_t p01 = packh2(e0, e1), p23 = packh2(e2, e3);
            int kt = nt >> 1;
            if (nt & 1) { pf[kt][2] = p01; pf[kt][3] = p23; }
            else        { pf[kt][0] = p01; pf[kt][1] = p23; }
        }
        sum0 += __shfl_xor_sync(0xffffffffu, sum0, 1);
        sum0 += __shfl_xor_sync(0xffffffffu, sum0, 2);
        sum1 += __shfl_xor_sync(0xffffffffu, sum1, 1);
        sum1 += __shfl_xor_sync(0xffffffffu, sum1, 2);
        l0 = l0 * a0 + sum0;
        l1 = l1 * a1 + sum1;

#pragma unroll
        for (int nt = 0; nt < 8; nt++) {
            o[nt][0] *= a0; o[nt][1] *= a0;
            o[nt][2] *= a1; o[nt][3] *= a1;
        }
#pragma unroll
        for (int kt = 0; kt < 4; kt++)
#pragma unroll
            for (int p = 0; p < 4; p++) {
                uint32_t bv[4];
                ldm_x4t(bv, Vc + (uint32_t)((kt * 16 + lr8) * LDHB
                                            + (p * 16 + lc8) * 2));
                mma_f16(o[2 * p],     pf[kt], &bv[0]);
                mma_f16(o[2 * p + 1], pf[kt], &bv[2]);
            }
    }

    const float i0 = 1.0f / l0, i1 = 1.0f / l1;
    const int b_ = bh >> 4, h = bh & 15;
    const int r0 = qblk * 128 + warp * 16 + g;
    const size_t tok0 = (size_t)b_ * SLEN + r0;
#pragma unroll
    for (int nt = 0; nt < 8; nt++) {
        int c = nt * 8 + 2 * t;
        *(uint32_t*)&O[tok0 * EMBED + h * 64 + c] =
            packh2(o[nt][0] * i0, o[nt][1] * i0);
        *(uint32_t*)&O[(tok0 + 8) * EMBED + h * 64 + c] =
            packh2(o[nt][2] * i1, o[nt][3] * i1);
    }
}

// ---------------------------------------------------------------------------
extern "C" void kernel_launch(void* const* d_in, const int* in_sizes, int n_in,
                              void* d_out, int out_size)
{
    const float* x    = (const float*)d_in[0];
    const float* Wqkv = (const float*)d_in[1];
    const float* Wout = (const float*)d_in[2];
    float* out = (float*)d_out;

    __half *Qp, *Kp, *Vp, *xp, *op, *w1, *w2;
    cudaGetSymbolAddress((void**)&Qp, g_Q);
    cudaGetSymbolAddress((void**)&Kp, g_K);
    cudaGetSymbolAddress((void**)&Vp, g_V);
    cudaGetSymbolAddress((void**)&xp, g_x);
    cudaGetSymbolAddress((void**)&op, g_o);
    cudaGetSymbolAddress((void**)&w1, g_w1);
    cudaGetSymbolAddress((void**)&w2, g_w2);

    static bool configured = false;
    if (!configured) {
        cudaFuncSetAttribute(attn_reg,
                             cudaFuncAttributeMaxDynamicSharedMemorySize, ATTN_SMEM);
        cudaFuncSetAttribute(gemm_f16<0>,
                             cudaFuncAttributeMaxDynamicSharedMemorySize, GEMM_SMEM);
        cudaFuncSetAttribute(gemm_f16<1>,
                             cudaFuncAttributeMaxDynamicSharedMemorySize, GEMM_SMEM);
        configured = true;
    }

    // 0) conversions (all fp16 single)
    int n4x = NTOK * EMBED / 4, n4q = EMBED * QKVN / 4, n4o = EMBED * EMBED / 4;
    conv_h<<<(n4x + 255) / 256, 256>>>(x, xp, n4x);
    conv_h<<<(n4q + 255) / 256, 256>>>(Wqkv, w1, n4q);
    conv_h<<<(n4o + 255) / 256, 256>>>(Wout, w2, n4o);

    // 1) QKV projection -> fp16 Q(scaled)/K/V
    dim3 g1(QKVN / 128, NTOK / 128);
    gemm_f16<0><<<g1, 256, GEMM_SMEM>>>(xp, w1, nullptr, Qp, Kp, Vp,
                                        NTOK, QKVN, EMBED);

    // 2) register FA2 -> fp16 O
    dim3 g2(SLEN / 128, BATCH * NHEAD);
    attn_reg<<<g2, 256, ATTN_SMEM>>>(Qp, Kp, Vp, op);

    // 3) output projection
    dim3 g3(EMBED / 128, NTOK / 128);
    gemm_f16<1><<<g3, 256, GEMM_SMEM>>>(op, w2, out, nullptr, nullptr, nullptr,
                                        NTOK, EMBED, EMBED);
}

// round 12
// speedup vs baseline: 1.6763x; 1.2842x over previous
#include <cuda_runtime.h>
#include <cuda_fp16.h>
#include <stdint.h>
#include <math.h>

#define BATCH 4
#define SLEN  2048
#define EMBED 1024
#define NHEAD 16
#define HDIM  64
#define NTOK  (BATCH * SLEN)     // 8192
#define QKVN  (3 * EMBED)        // 3072

// packed per-head QKV: [token][h*192 + {q:0..63, k:64..127, v:128..191}]
__device__ __half g_qkv[(size_t)NTOK * QKVN];
__device__ __half g_x[(size_t)NTOK * EMBED];
__device__ __half g_o[(size_t)NTOK * EMBED];
__device__ __half g_w1[(size_t)EMBED * QKVN];   // permuted cols + q-scale folded
__device__ __half g_w2[(size_t)EMBED * EMBED];

// ------------------------------ helpers ------------------------------------
__device__ __forceinline__ uint32_t s2u(const void* p) {
    uint32_t a;
    asm("{ .reg .u64 t; cvta.to.shared.u64 t, %1; cvt.u32.u64 %0, t; }" : "=r"(a) : "l"(p));
    return a;
}
__device__ __forceinline__ void mma_f16(float* d, const uint32_t* a, const uint32_t* b) {
    asm volatile("mma.sync.aligned.m16n8k16.row.col.f32.f16.f16.f32 "
        "{%0,%1,%2,%3},{%4,%5,%6,%7},{%8,%9},{%0,%1,%2,%3};"
        : "+f"(d[0]), "+f"(d[1]), "+f"(d[2]), "+f"(d[3])
        : "r"(a[0]), "r"(a[1]), "r"(a[2]), "r"(a[3]), "r"(b[0]), "r"(b[1]));
}
__device__ __forceinline__ void ldm_x4(uint32_t* r, uint32_t a) {
    asm volatile("ldmatrix.sync.aligned.m8n8.x4.shared.b16 {%0,%1,%2,%3},[%4];"
        : "=r"(r[0]), "=r"(r[1]), "=r"(r[2]), "=r"(r[3]) : "r"(a));
}
__device__ __forceinline__ void ldm_x4t(uint32_t* r, uint32_t a) {
    asm volatile("ldmatrix.sync.aligned.m8n8.x4.trans.shared.b16 {%0,%1,%2,%3},[%4];"
        : "=r"(r[0]), "=r"(r[1]), "=r"(r[2]), "=r"(r[3]) : "r"(a));
}
__device__ __forceinline__ uint32_t packh2(float a, float b) {
    __half2 h = __floats2half2_rn(a, b);
    return *(uint32_t*)&h;
}
#define CP16(sa, gp) \
    asm volatile("cp.async.cg.shared.global [%0], [%1], 16;" :: "r"(sa), "l"(gp) : "memory")
#define CP_COMMIT()  asm volatile("cp.async.commit_group;" ::: "memory")
#define CP_WAIT(n)   asm volatile("cp.async.wait_group %0;" :: "n"(n) : "memory")

// ------------------------- conversion kernels ------------------------------
__global__ void __launch_bounds__(256)
conv_h(const float* __restrict__ X, __half* __restrict__ Y, int n4)
{
    int i = blockIdx.x * blockDim.x + threadIdx.x;
    if (i >= n4) return;
    float4 v = ((const float4*)X)[i];
    ((uint2*)Y)[i] = make_uint2(packh2(v.x, v.y), packh2(v.z, v.w));
}

// W_QKV [1024][3072]: col' = h*192 + w*64 + d  <-  col = h*192 + 3d + w,
// with q-columns (w==0) pre-scaled by 1/32 (exact exponent shift).
__global__ void __launch_bounds__(256)
conv_w1p(const float* __restrict__ W, __half* __restrict__ Wp)
{
    int i = blockIdx.x * blockDim.x + threadIdx.x;   // one uint32 (2 out halfs)
    if (i >= EMBED * (QKVN / 2)) return;
    int k  = i / (QKVN / 2);
    int c2 = i - k * (QKVN / 2);
    int col0 = c2 * 2;
    int h = col0 / 192;
    int rem = col0 - h * 192;
    int w = rem >> 6, d = rem & 63;
    const float* src = W + (size_t)k * QKVN + h * 192 + 3 * d + w;
    float sc = (w == 0) ? 0.03125f : 1.0f;
    ((uint32_t*)Wp)[i] = packh2(src[0] * sc, src[3] * sc);
}

// ---------------------------------------------------------------------------
// fp16 GEMM: C = A@B. BM=BN=128, BK=64 per stage, 3-stage cp.async pipeline,
// single barrier per iteration, 2 CTAs/SM. 8 warps 2x4 (warp 64x32).
// MODE 0: fp16 store.  MODE 1: fp32 store.
// ---------------------------------------------------------------------------
#define ASTG 18432u                 // A tile: 128 rows * 144B
#define GSTG 35840u                 // stage = A + B(64*272)
#define GEMM_SMEM (3 * 35840)

template <int MODE>
__global__ void __launch_bounds__(256, 2)
gemm_f16(const __half* __restrict__ A, const __half* __restrict__ B,
         __half* __restrict__ Ch, float* __restrict__ Cf, int M, int N, int K)
{
    extern __shared__ char gsm[];
    const uint32_t smb = s2u(gsm);

    const int tid = threadIdx.x, lane = tid & 31, warp = tid >> 5;
    const int wm = warp >> 2, wn = warp & 3;
    const int g = lane >> 2, t = lane & 3;
    const int m0 = blockIdx.y * 128, n0 = blockIdx.x * 128;

    const int arow = wm * 64 + (lane & 7) + ((lane >> 3) & 1) * 8;
    const int acol = (lane >> 4) * 8;
    const int brow = (lane & 7) + ((lane >> 3) & 1) * 8;
    const int bcol = (lane >> 4) * 8;

    float acc[4][4][4];
#pragma unroll
    for (int mt = 0; mt < 4; mt++)
#pragma unroll
        for (int nt = 0; nt < 4; nt++)
#pragma unroll
            for (int e = 0; e < 4; e++) acc[mt][nt][e] = 0.0f;

    const int KIT = K / 64;

    auto load_stage = [&](int it) {
        const uint32_t base = smb + (uint32_t)(it % 3) * GSTG;
        const int k0 = it * 64;
#pragma unroll
        for (int r = 0; r < 4; r++) {            // A: 128 rows x 64 halfs
            int id = tid + r * 256;
            int row = id >> 3, ch = id & 7;
            CP16(base + (uint32_t)(row * 144 + ch * 16),
                 A + (size_t)(m0 + row) * K + k0 + ch * 8);
        }
#pragma unroll
        for (int r = 0; r < 4; r++) {            // B: 64 rows x 128 halfs
            int id = tid + r * 256;
            int row = id >> 4, ch = id & 15;
            CP16(base + ASTG + (uint32_t)(row * 272 + ch * 16),
                 B + (size_t)(k0 + row) * N + n0 + ch * 8);
        }
        CP_COMMIT();
    };

    load_stage(0);
    load_stage(1);

#pragma unroll 1
    for (int it = 0; it < KIT; it++) {
        const uint32_t cur = smb + (uint32_t)(it % 3) * GSTG;
        if (it + 1 < KIT) { CP_WAIT(1); } else { CP_WAIT(0); }
        __syncthreads();                        // all warps done reading it-1
        if (it + 2 < KIT) load_stage(it + 2);   // overwrites (it-1)%3: safe

#pragma unroll
        for (int ks = 0; ks < 4; ks++) {
            uint32_t ah[4][4];
#pragma unroll
            for (int mt = 0; mt < 4; mt++)
                ldm_x4(ah[mt], cur + (uint32_t)((arow + mt * 16) * 144
                                                + (acol + ks * 16) * 2));
            uint32_t bb[2][4];
#pragma unroll
            for (int p = 0; p < 2; p++)
                ldm_x4t(bb[p], cur + ASTG
                        + (uint32_t)((ks * 16 + brow) * 272
                                     + (wn * 32 + p * 16 + bcol) * 2));
#pragma unroll
            for (int p = 0; p < 2; p++)
#pragma unroll
                for (int sub = 0; sub < 2; sub++) {
                    const int nt = 2 * p + sub;
#pragma unroll
                    for (int mt = 0; mt < 4; mt++)
                        mma_f16(acc[mt][nt], ah[mt], &bb[p][sub * 2]);
                }
        }
    }

#pragma unroll
    for (int mt = 0; mt < 4; mt++)
#pragma unroll
        for (int nt = 0; nt < 4; nt++) {
            size_t r = (size_t)(m0 + wm * 64 + mt * 16 + g);
            int    c = n0 + wn * 32 + nt * 8 + 2 * t;
            if (MODE == 0) {
                *(uint32_t*)&Ch[r * N + c]       = packh2(acc[mt][nt][0], acc[mt][nt][1]);
                *(uint32_t*)&Ch[(r + 8) * N + c] = packh2(acc[mt][nt][2], acc[mt][nt][3]);
            } else {
                *(float2*)&Cf[r * N + c]       = make_float2(acc[mt][nt][0], acc[mt][nt][1]);
                *(float2*)&Cf[(r + 8) * N + c] = make_float2(acc[mt][nt][2], acc[mt][nt][3]);
            }
        }
}

// ---------------------------------------------------------------------------
// Register FA2 over packed QKV. BQ=128 (8 warps x 16 rows), BKEY=64, D=64.
// K|V merged tile (272B rows), 3-stage cp.async, single barrier per iter.
// ---------------------------------------------------------------------------
#define QSTG 18432u                  // Q: 128 rows * 144B
#define KVST 17408u                  // K|V: 64 rows * 272B
#define ATTN_SMEM (QSTG + 3 * KVST)  // 70656

__global__ void __launch_bounds__(256, 2)
attn_reg(const __half* __restrict__ QKV, __half* __restrict__ O)
{
    extern __shared__ char smc[];
    const uint32_t Qb = s2u(smc);
    const uint32_t KV0 = Qb + QSTG;

    const int tid = threadIdx.x, lane = tid & 31, warp = tid >> 5;
    const int g = lane >> 2, t = lane & 3;
    const int lr8 = (lane & 7) + ((lane >> 3) & 1) * 8;
    const int lc8 = (lane >> 4) * 8;
    const int qblk = blockIdx.x, bh = blockIdx.y;
    const int b_ = bh >> 4, h = bh & 15;

    // packed bases (halfs): Q at h*192, K|V at h*192+64 (128 contiguous halfs)
    const __half* Qg  = QKV + ((size_t)b_ * SLEN + qblk * 128) * QKVN + h * 192;
    const __half* KVg = QKV + ((size_t)b_ * SLEN) * QKVN + h * 192 + 64;

    auto load_kv = [&](int kb) {
        const uint32_t base = KV0 + (uint32_t)(kb % 3) * KVST;
        const __half* src = KVg + (size_t)kb * 64 * QKVN;
#pragma unroll
        for (int r = 0; r < 4; r++) {
            int id = tid + r * 256;                 // 0..1023
            int row = id >> 4, ch = id & 15;        // 16 chunks = K(8) + V(8)
            CP16(base + (uint32_t)(row * 272 + ch * 16),
                 src + (size_t)row * QKVN + ch * 8);
        }
        CP_COMMIT();
    };

#pragma unroll
    for (int r = 0; r < 4; r++) {
        int id = tid + r * 256;
        int row = id >> 3, ch = id & 7;
        CP16(Qb + (uint32_t)(row * 144 + ch * 16),
             Qg + (size_t)row * QKVN + ch * 8);
    }
    CP_COMMIT();
    load_kv(0);
    load_kv(1);
    CP_WAIT(2);             // Q resident
    __syncthreads();

    uint32_t qf[4][4];
#pragma unroll
    for (int kt = 0; kt < 4; kt++)
        ldm_x4(qf[kt], Qb + (uint32_t)((warp * 16 + lr8) * 144 + (kt * 16 + lc8) * 2));

    float m0 = -1e30f, m1 = -1e30f, l0 = 0.0f, l1 = 0.0f;
    float o[8][4];
#pragma unroll
    for (int nt = 0; nt < 8; nt++)
#pragma unroll
        for (int e = 0; e < 4; e++) o[nt][e] = 0.0f;

    const int NKB = SLEN / 64;
#pragma unroll 1
    for (int kb = 0; kb < NKB; kb++) {
        const uint32_t Kc = KV0 + (uint32_t)(kb % 3) * KVST;
        if (kb + 1 < NKB) { CP_WAIT(1); } else { CP_WAIT(0); }
        __syncthreads();
        if (kb + 2 < NKB) load_kv(kb + 2);

        float s[8][4];
#pragma unroll
        for (int nt = 0; nt < 8; nt++)
#pragma unroll
            for (int e = 0; e < 4; e++) s[nt][e] = 0.0f;
#pragma unroll
        for (int kt = 0; kt < 4; kt++)
#pragma unroll
            for (int p = 0; p < 4; p++) {
                uint32_t bk[4];
                ldm_x4(bk, Kc + (uint32_t)((p * 16 + lc8 + (lane & 7)) * 272
                                           + (kt * 16 + ((lane >> 3) & 1) * 8) * 2));
                mma_f16(s[2 * p],     qf[kt], &bk[0]);
                mma_f16(s[2 * p + 1], qf[kt], &bk[2]);
            }

        float mx0 = -1e30f, mx1 = -1e30f;
#pragma unroll
        for (int nt = 0; nt < 8; nt++) {
            mx0 = fmaxf(mx0, fmaxf(s[nt][0], s[nt][1]));
            mx1 = fmaxf(mx1, fmaxf(s[nt][2], s[nt][3]));
        }
        mx0 = fmaxf(mx0, __shfl_xor_sync(0xffffffffu, mx0, 1));
        mx0 = fmaxf(mx0, __shfl_xor_sync(0xffffffffu, mx0, 2));
        mx1 = fmaxf(mx1, __shfl_xor_sync(0xffffffffu, mx1, 1));
        mx1 = fmaxf(mx1, __shfl_xor_sync(0xffffffffu, mx1, 2));
        float mn0 = fmaxf(m0, mx0), mn1 = fmaxf(m1, mx1);
        float a0 = __expf(m0 - mn0), a1 = __expf(m1 - mn1);
        m0 = mn0; m1 = mn1;

        float sum0 = 0.0f, sum1 = 0.0f;
        uint32_t pf[4][4];
#pragma unroll
        for (int nt = 0; nt < 8; nt++) {
            float e0 = __expf(s[nt][0] - mn0), e1 = __expf(s[nt][1] - mn0);
            float e2 = __expf(s[nt][2] - mn1), e3 = __expf(s[nt][3] - mn1);
            sum0 += e0 + e1; sum1 += e2 + e3;
            uint32_t p01 = packh2(e0, e1), p23 = packh2(e2, e3);
            int kt = nt >> 1;
            if (nt & 1) { pf[kt][2] = p01; pf[kt][3] = p23; }
            else        { pf[kt][0] = p01; pf[kt][1] = p23; }
        }
        sum0 += __shfl_xor_sync(0xffffffffu, sum0, 1);
        sum0 += __shfl_xor_sync(0xffffffffu, sum0, 2);
        sum1 += __shfl_xor_sync(0xffffffffu, sum1, 1);
        sum1 += __shfl_xor_sync(0xffffffffu, sum1, 2);
        l0 = l0 * a0 + sum0;
        l1 = l1 * a1 + sum1;

#pragma unroll
        for (int nt = 0; nt < 8; nt++) {
            o[nt][0] *= a0; o[nt][1] *= a0;
            o[nt][2] *= a1; o[nt][3] *= a1;
        }
#pragma unroll
        for (int kt = 0; kt < 4; kt++)
#pragma unroll
            for (int p = 0; p < 4; p++) {
                uint32_t bv[4];
                ldm_x4t(bv, Kc + (uint32_t)((kt * 16 + lr8) * 272 + 128
                                            + (p * 16 + lc8) * 2));
                mma_f16(o[2 * p],     pf[kt], &bv[0]);
                mma_f16(o[2 * p + 1], pf[kt], &bv[2]);
            }
    }

    const float i0 = 1.0f / l0, i1 = 1.0f / l1;
    const int r0 = qblk * 128 + warp * 16 + g;
    const size_t tok0 = (size_t)b_ * SLEN + r0;
#pragma unroll
    for (int nt = 0; nt < 8; nt++) {
        int c = nt * 8 + 2 * t;
        *(uint32_t*)&O[tok0 * EMBED + h * 64 + c] =
            packh2(o[nt][0] * i0, o[nt][1] * i0);
        *(uint32_t*)&O[(tok0 + 8) * EMBED + h * 64 + c] =
            packh2(o[nt][2] * i1, o[nt][3] * i1);
    }
}

// ---------------------------------------------------------------------------
extern "C" void kernel_launch(void* const* d_in, const int* in_sizes, int n_in,
                              void* d_out, int out_size)
{
    const float* x    = (const float*)d_in[0];
    const float* Wqkv = (const float*)d_in[1];
    const float* Wout = (const float*)d_in[2];
    float* out = (float*)d_out;

    __half *qkv, *xp, *op, *w1, *w2;
    cudaGetSymbolAddress((void**)&qkv, g_qkv);
    cudaGetSymbolAddress((void**)&xp, g_x);
    cudaGetSymbolAddress((void**)&op, g_o);
    cudaGetSymbolAddress((void**)&w1, g_w1);
    cudaGetSymbolAddress((void**)&w2, g_w2);

    static bool configured = false;
    if (!configured) {
        cudaFuncSetAttribute(attn_reg,
                             cudaFuncAttributeMaxDynamicSharedMemorySize, ATTN_SMEM);
        cudaFuncSetAttribute(gemm_f16<0>,
                             cudaFuncAttributeMaxDynamicSharedMemorySize, GEMM_SMEM);
        cudaFuncSetAttribute(gemm_f16<1>,
                             cudaFuncAttributeMaxDynamicSharedMemorySize, GEMM_SMEM);
        configured = true;
    }

    // 0) conversions
    int n4x = NTOK * EMBED / 4, n2q = EMBED * (QKVN / 2), n4o = EMBED * EMBED / 4;
    conv_h<<<(n4x + 255) / 256, 256>>>(x, xp, n4x);
    conv_w1p<<<(n2q + 255) / 256, 256>>>(Wqkv, w1);
    conv_h<<<(n4o + 255) / 256, 256>>>(Wout, w2, n4o);

    // 1) QKV projection -> packed per-head fp16 (Q already scaled via W)
    dim3 g1(QKVN / 128, NTOK / 128);
    gemm_f16<0><<<g1, 256, GEMM_SMEM>>>(xp, w1, qkv, nullptr, NTOK, QKVN, EMBED);

    // 2) register FA2 -> fp16 O
    dim3 g2(SLEN / 128, BATCH * NHEAD);
    attn_reg<<<g2, 256, ATTN_SMEM>>>(qkv, op);

    // 3) output projection -> fp32 out
    dim3 g3(EMBED / 128, NTOK / 128);
    gemm_f16<1><<<g3, 256, GEMM_SMEM>>>(op, w2, nullptr, out, NTOK, EMBED, EMBED);
}